// round 2
// baseline (speedup 1.0000x reference)
#include <cuda_runtime.h>
#include <math.h>

#define S 128
#define B 1024
#define T 96
#define E 64
#define H 200
#define HH 100
#define ATT 200
#define DEC_IN 440
#define XCAT 640

// ---------------- scratch (device globals; no allocations allowed) -------------
__device__ float g_emb[S * B * E];          // [S*B, 64]
__device__ float g_xw_f[S * B * 4 * HH];    // [S*B, 400]
__device__ float g_xw_b[S * B * 4 * HH];
__device__ float g_hs_f[S * B * HH];        // [S, B, 100]
__device__ float g_hs_b[S * B * HH];
__device__ float g_cf[B * HH];
__device__ float g_cb[B * HH];
__device__ float g_enc[B * S * H];          // [B, S, 200] row-contiguous per b
__device__ float g_Wcat[4 * H * XCAT];      // [800, 640] = [Wih_d | Whh_d]
__device__ float g_WattnT[H * H];           // W_attn transposed
__device__ float g_h[B * H];
__device__ float g_c[B * H];
__device__ float g_Hbuf[T * B * H];
__device__ float g_xcat[B * XCAT];
__device__ float g_z[B * 4 * H];
__device__ float g_gtil[B * H];
__device__ float g_cath[B * 2 * H];

__device__ __forceinline__ float sigf(float x) { return 1.f / (1.f + expf(-x)); }

// ---------------- embedding ----------------
__global__ void k_embed(const int* __restrict__ sent, const float* __restrict__ src_emb) {
    int i = blockIdx.x * blockDim.x + threadIdx.x;
    if (i < S * B * E) {
        int sb = i >> 6;
        int e = i & 63;
        g_emb[i] = src_emb[(size_t)sent[sb] * E + e];
    }
}

// ---------------- generic SGEMM: C[M,N] = A[M,K] @ W[N,K]^T (+bias)(+tanh) ------
#define BM 64
#define BN 64
#define BK 16
__global__ void __launch_bounds__(256) k_sgemm(
    const float* __restrict__ A, const float* __restrict__ W,
    const float* __restrict__ bias, float* __restrict__ C,
    int M, int N, int K, int act)
{
    __shared__ float As[BK][BM + 4];
    __shared__ float Ws[BK][BN + 4];
    int bm = blockIdx.y * BM, bn = blockIdx.x * BN;
    int tid = threadIdx.x;
    int tx = tid & 15, ty = tid >> 4;  // tx: k-col on load / n-group on compute
    float acc[4][4] = {};

    for (int k0 = 0; k0 < K; k0 += BK) {
#pragma unroll
        for (int i = 0; i < 4; i++) {
            int r = ty + i * 16;
            int m = bm + r, k = k0 + tx, n = bn + r;
            As[tx][r] = (m < M && k < K) ? A[(size_t)m * K + k] : 0.f;
            Ws[tx][r] = (n < N && k < K) ? W[(size_t)n * K + k] : 0.f;
        }
        __syncthreads();
#pragma unroll
        for (int kk = 0; kk < BK; kk++) {
            float a[4], w[4];
#pragma unroll
            for (int i = 0; i < 4; i++) a[i] = As[kk][ty * 4 + i];
#pragma unroll
            for (int j = 0; j < 4; j++) w[j] = Ws[kk][tx * 4 + j];
#pragma unroll
            for (int i = 0; i < 4; i++)
#pragma unroll
                for (int j = 0; j < 4; j++) acc[i][j] += a[i] * w[j];
        }
        __syncthreads();
    }
#pragma unroll
    for (int i = 0; i < 4; i++) {
        int m = bm + ty * 4 + i;
        if (m >= M) continue;
#pragma unroll
        for (int j = 0; j < 4; j++) {
            int n = bn + tx * 4 + j;
            if (n >= N) continue;
            float v = acc[i][j] + (bias ? bias[n] : 0.f);
            if (act) v = tanhf(v);
            C[(size_t)m * N + n] = v;
        }
    }
}

// ---------------- fused bidirectional LSTM encoder ----------------
// 148 blocks: 0..73 forward, 74..147 backward. Each block owns 14 batch rows,
// keeps Whh (160KB) + h (local) in SMEM, runs all 128 steps. No grid sync needed
// (batch rows are independent). c lives in registers.
#define ENC_BPB 14
#define ENC_SMEM_FLOATS (40000 + ENC_BPB * HH + ENC_BPB * 4 * HH)
__global__ void __launch_bounds__(256) k_encoder(const float* __restrict__ Whh_f,
                                                 const float* __restrict__ Whh_b)
{
    extern __shared__ float sm[];
    float* sW = sm;                       // 40000: Whh [400,100]
    float* sh = sm + 40000;               // 1400: h for owned b's
    float* sz = sm + 40000 + ENC_BPB * HH;// 5600: z staging

    int dir = blockIdx.x >= 74;
    int lg = dir ? blockIdx.x - 74 : blockIdx.x;
    const float* Whh = dir ? Whh_b : Whh_f;
    const float* xw = dir ? g_xw_b : g_xw_f;
    float* hs = dir ? g_hs_b : g_hs_f;
    float* cg = dir ? g_cb : g_cf;
    int b0 = lg * ENC_BPB;
    int nb = min(ENC_BPB, B - b0);
    int tid = threadIdx.x;

    for (int i = tid; i < 40000; i += 256) sW[i] = Whh[i];
    for (int i = tid; i < ENC_BPB * HH; i += 256) sh[i] = 0.f;
    float creg[6] = {0.f, 0.f, 0.f, 0.f, 0.f, 0.f};
    __syncthreads();

    for (int t = 0; t < S; t++) {
        int tt = dir ? (S - 1 - t) : t;
        // GEMM phase: z[b, 0..400) = xw[tt,b,:] + Whh @ h[b]
        if (tid < 200) {
            int jg = tid % 100;          // rows 4jg..4jg+3
            int bgb = (tid / 100) * 7;   // 7 local b's
            float acc[4][7];
#pragma unroll
            for (int r = 0; r < 4; r++)
#pragma unroll
                for (int bb = 0; bb < 7; bb++) {
                    int bl = bgb + bb;
                    acc[r][bb] = (bl < nb)
                        ? xw[((size_t)tt * B + (b0 + bl)) * 400 + 4 * jg + r] : 0.f;
                }
            const float4* shv = (const float4*)sh;
            const float4* swv = (const float4*)sW;
            for (int k4 = 0; k4 < 25; k4++) {
                float4 w0 = swv[(4 * jg + 0) * 25 + k4];
                float4 w1 = swv[(4 * jg + 1) * 25 + k4];
                float4 w2 = swv[(4 * jg + 2) * 25 + k4];
                float4 w3 = swv[(4 * jg + 3) * 25 + k4];
#pragma unroll
                for (int bb = 0; bb < 7; bb++) {
                    float4 hv = shv[(bgb + bb) * 25 + k4];
                    acc[0][bb] += w0.x * hv.x + w0.y * hv.y + w0.z * hv.z + w0.w * hv.w;
                    acc[1][bb] += w1.x * hv.x + w1.y * hv.y + w1.z * hv.z + w1.w * hv.w;
                    acc[2][bb] += w2.x * hv.x + w2.y * hv.y + w2.z * hv.z + w2.w * hv.w;
                    acc[3][bb] += w3.x * hv.x + w3.y * hv.y + w3.z * hv.z + w3.w * hv.w;
                }
            }
#pragma unroll
            for (int r = 0; r < 4; r++)
#pragma unroll
                for (int bb = 0; bb < 7; bb++)
                    if (bgb + bb < nb) sz[(bgb + bb) * 400 + 4 * jg + r] = acc[r][bb];
        }
        __syncthreads();
        // cell phase
#pragma unroll
        for (int i = 0; i < 6; i++) {
            int pp = tid + i * 256;
            if (pp < nb * HH) {
                int bl = pp / HH, j = pp % HH;
                float zi = sz[bl * 400 + j];
                float zf = sz[bl * 400 + 100 + j];
                float zg = sz[bl * 400 + 200 + j];
                float zo = sz[bl * 400 + 300 + j];
                float cn = sigf(zf) * creg[i] + sigf(zi) * tanhf(zg);
                float hn = sigf(zo) * tanhf(cn);
                creg[i] = cn;
                sh[bl * HH + j] = hn;
                hs[((size_t)tt * B + b0 + bl) * HH + j] = hn;
            }
        }
        __syncthreads();
    }
#pragma unroll
    for (int i = 0; i < 6; i++) {
        int pp = tid + i * 256;
        if (pp < nb * HH) cg[(b0 + pp / HH) * HH + pp % HH] = creg[i];
    }
}

// ---------------- enc concat + transpose to [B, S, 200] ----------------
__global__ void k_concat() {
    int e = blockIdx.x * blockDim.x + threadIdx.x;
    if (e >= B * S * H) return;
    int b = e / (S * H);
    int r = e % (S * H);
    int s = r / H, j = r % H;
    g_enc[e] = (j < HH) ? g_hs_f[((size_t)s * B + b) * HH + j]
                        : g_hs_b[((size_t)s * B + b) * HH + (j - HH)];
}

// ---------------- weight prep: Wcat = [Wih_d | Whh_d], WattnT ----------------
__global__ void k_prep(const float* __restrict__ Wih_d, const float* __restrict__ Whh_d,
                       const float* __restrict__ W_attn) {
    int i = blockIdx.x * blockDim.x + threadIdx.x;
    if (i < 4 * H * XCAT) {
        int n = i / XCAT, k = i % XCAT;
        g_Wcat[i] = (k < DEC_IN) ? Wih_d[n * DEC_IN + k] : Whh_d[n * H + (k - DEC_IN)];
    } else {
        int i2 = i - 4 * H * XCAT;
        if (i2 < H * H) {
            int k = i2 / H, j = i2 % H;
            g_WattnT[i2] = W_attn[j * H + k];
        }
    }
}

// ---------------- decoder h0/c0 init (torch h0.view(-1,H) quirk) ----------------
__global__ void k_dec_init() {
    int e = blockIdx.x * blockDim.x + threadIdx.x;
    if (e >= B * H) return;
    int r = e / H, k = e % H;
    int hi = (k >= HH) ? 1 : 0;
    int j = k - hi * HH;
    if (r < 512) {
        int b = 2 * r + hi;
        g_h[e] = g_hs_f[((size_t)(S - 1) * B + b) * HH + j];
        g_c[e] = g_cf[b * HH + j];
    } else {
        int b = 2 * (r - 512) + hi;
        g_h[e] = g_hs_b[(size_t)b * HH + j];  // hs_b[t=0]
        g_c[e] = g_cb[b * HH + j];
    }
}

// ---------------- decoder: build xcat = [inp(440) | h(200)] ----------------
__global__ void k_build_xcat(int t, const int* __restrict__ is_prod,
                             const int* __restrict__ prod_ids, const int* __restrict__ prim_ids,
                             const int* __restrict__ field_ids, const int* __restrict__ parent_t,
                             const float* __restrict__ actprod_emb, const float* __restrict__ prim_emb,
                             const float* __restrict__ field_emb, const float* __restrict__ out) {
    int e = blockIdx.x * blockDim.x + threadIdx.x;
    if (e >= B * XCAT) return;
    int b = e / XCAT, col = e % XCAT;
    float v;
    if (col >= DEC_IN) {
        v = g_h[b * H + (col - DEC_IN)];
    } else if (t == 0) {
        v = 0.f;
    } else if (col < 32) {
        int idx = t * B + b;
        v = (is_prod[idx] == 1) ? actprod_emb[prod_ids[idx] * 32 + col]
                                : prim_emb[prim_ids[idx] * 32 + col];
    } else if (col < 232) {
        v = out[(size_t)(t - 1) * B * ATT + b * ATT + (col - 32)];
    } else if (col < 240) {
        v = field_emb[field_ids[t * B + b] * 8 + (col - 232)];
    } else {
        int pt = parent_t[t * B + b];
        v = g_Hbuf[((size_t)pt * B + b) * H + (col - 240)];
    }
    g_xcat[e] = v;
}

// ---------------- decoder LSTM cell ----------------
__global__ void k_cell(int t) {
    int e = blockIdx.x * blockDim.x + threadIdx.x;
    if (e >= B * H) return;
    int b = e / H, j = e % H;
    const float* z = g_z + (size_t)b * 4 * H;
    float cn = sigf(z[H + j]) * g_c[e] + sigf(z[j]) * tanhf(z[2 * H + j]);
    float hn = sigf(z[3 * H + j]) * tanhf(cn);
    g_c[e] = cn;
    g_h[e] = hn;
    g_Hbuf[(size_t)t * B * H + e] = hn;
}

// ---------------- attention: scores (via gtil) + softmax + ctx, per batch row ----
// block b stages enc[b] (128x200 = 100KB) in SMEM; scores AND ctx read it from SMEM.
#define ATTN_SMEM_FLOATS (S * H + H + S)
__global__ void __launch_bounds__(256) k_attn() {
    extern __shared__ float smem[];
    float* senc = smem;           // 25600
    float* sg = smem + S * H;     // 200
    float* sp = sg + H;           // 128 scores
    int b = blockIdx.x, tid = threadIdx.x;

    const float4* src = (const float4*)(g_enc + (size_t)b * S * H);
    float4* dst = (float4*)senc;
    for (int i = tid; i < S * H / 4; i += 256) dst[i] = src[i];
    if (tid < H) sg[tid] = g_gtil[b * H + tid];
    __syncthreads();

    int warp = tid >> 5, lane = tid & 31;
    for (int s = warp; s < S; s += 8) {
        float acc = 0.f;
        for (int k = lane; k < H; k += 32) acc += senc[s * H + k] * sg[k];
#pragma unroll
        for (int o = 16; o; o >>= 1) acc += __shfl_xor_sync(0xffffffffu, acc, o);
        if (lane == 0) sp[s] = acc;
    }
    __syncthreads();
    if (warp == 0) {
        float v0 = sp[lane], v1 = sp[lane + 32], v2 = sp[lane + 64], v3 = sp[lane + 96];
        float m = fmaxf(fmaxf(v0, v1), fmaxf(v2, v3));
#pragma unroll
        for (int o = 16; o; o >>= 1) m = fmaxf(m, __shfl_xor_sync(0xffffffffu, m, o));
        float e0 = expf(v0 - m), e1 = expf(v1 - m), e2 = expf(v2 - m), e3 = expf(v3 - m);
        float ssum = e0 + e1 + e2 + e3;
#pragma unroll
        for (int o = 16; o; o >>= 1) ssum += __shfl_xor_sync(0xffffffffu, ssum, o);
        float inv = 1.f / ssum;
        sp[lane] = e0 * inv; sp[lane + 32] = e1 * inv;
        sp[lane + 64] = e2 * inv; sp[lane + 96] = e3 * inv;
    }
    __syncthreads();
    if (tid < H) {
        float acc = 0.f;
#pragma unroll 8
        for (int s = 0; s < S; s++) acc += sp[s] * senc[s * H + tid];
        g_cath[b * 2 * H + tid] = acc;
        g_cath[b * 2 * H + H + tid] = g_h[b * H + tid];
    }
}

// ---------------- host launch ----------------
static void sgemm(const float* A, const float* W, const float* bias, float* C,
                  int M, int N, int K, int act) {
    dim3 grid((N + BN - 1) / BN, (M + BM - 1) / BM);
    k_sgemm<<<grid, 256>>>(A, W, bias, C, M, N, K, act);
}

extern "C" void kernel_launch(void* const* d_in, const int* in_sizes, int n_in,
                              void* d_out, int out_size) {
    const int* sentences  = (const int*)d_in[0];
    const int* is_prod    = (const int*)d_in[1];
    const int* prod_ids   = (const int*)d_in[2];
    const int* prim_ids   = (const int*)d_in[3];
    const int* field_ids  = (const int*)d_in[4];
    const int* parent_t   = (const int*)d_in[5];
    const float* src_emb  = (const float*)d_in[6];
    const float* actprod_emb = (const float*)d_in[7];
    const float* prim_emb = (const float*)d_in[8];
    const float* field_emb = (const float*)d_in[9];
    const float* Wih_f = (const float*)d_in[10];
    const float* Whh_f = (const float*)d_in[11];
    const float* b_f   = (const float*)d_in[12];
    const float* Wih_b = (const float*)d_in[13];
    const float* Whh_b = (const float*)d_in[14];
    const float* b_b   = (const float*)d_in[15];
    const float* Wih_d = (const float*)d_in[16];
    const float* Whh_d = (const float*)d_in[17];
    const float* b_d   = (const float*)d_in[18];
    const float* W_attn = (const float*)d_in[19];
    const float* W_av   = (const float*)d_in[20];
    float* out = (float*)d_out;

    // symbol addresses for GEMM args
    void *p_emb, *p_xwf, *p_xwb, *p_xcat, *p_Wcat, *p_z, *p_h, *p_WaT, *p_gtil, *p_cath;
    cudaGetSymbolAddress(&p_emb, g_emb);
    cudaGetSymbolAddress(&p_xwf, g_xw_f);
    cudaGetSymbolAddress(&p_xwb, g_xw_b);
    cudaGetSymbolAddress(&p_xcat, g_xcat);
    cudaGetSymbolAddress(&p_Wcat, g_Wcat);
    cudaGetSymbolAddress(&p_z, g_z);
    cudaGetSymbolAddress(&p_h, g_h);
    cudaGetSymbolAddress(&p_WaT, g_WattnT);
    cudaGetSymbolAddress(&p_gtil, g_gtil);
    cudaGetSymbolAddress(&p_cath, g_cath);

    cudaFuncSetAttribute(k_encoder, cudaFuncAttributeMaxDynamicSharedMemorySize,
                         ENC_SMEM_FLOATS * 4);
    cudaFuncSetAttribute(k_attn, cudaFuncAttributeMaxDynamicSharedMemorySize,
                         ATTN_SMEM_FLOATS * 4);

    // 1) embedding
    k_embed<<<(S * B * E + 255) / 256, 256>>>(sentences, src_emb);
    // 2) input projections for both LSTM directions
    sgemm((const float*)p_emb, Wih_f, b_f, (float*)p_xwf, S * B, 4 * HH, E, 0);
    sgemm((const float*)p_emb, Wih_b, b_b, (float*)p_xwb, S * B, 4 * HH, E, 0);
    // 3) bidirectional encoder (single fused kernel, 148 blocks)
    k_encoder<<<148, 256, ENC_SMEM_FLOATS * 4>>>(Whh_f, Whh_b);
    // 4) enc = concat/transpose
    k_concat<<<(B * S * H + 255) / 256, 256>>>();
    // 5) weight prep + decoder init
    k_prep<<<(4 * H * XCAT + H * H + 255) / 256, 256>>>(Wih_d, Whh_d, W_attn);
    k_dec_init<<<(B * H + 255) / 256, 256>>>();

    // 6) decoder loop
    for (int t = 0; t < T; t++) {
        k_build_xcat<<<(B * XCAT + 255) / 256, 256>>>(t, is_prod, prod_ids, prim_ids,
                                                      field_ids, parent_t, actprod_emb,
                                                      prim_emb, field_emb, out);
        sgemm((const float*)p_xcat, (const float*)p_Wcat, b_d, (float*)p_z,
              B, 4 * H, XCAT, 0);
        k_cell<<<(B * H + 255) / 256, 256>>>(t);
        sgemm((const float*)p_h, (const float*)p_WaT, nullptr, (float*)p_gtil,
              B, H, H, 0);
        k_attn<<<B, 256, ATTN_SMEM_FLOATS * 4>>>();
        sgemm((const float*)p_cath, W_av, nullptr, out + (size_t)t * B * ATT,
              B, ATT, 2 * H, 1);
    }
}

// round 3
// speedup vs baseline: 1.1728x; 1.1728x over previous
#include <cuda_runtime.h>
#include <math.h>

#define S 128
#define B 1024
#define T 96
#define E 64
#define H 200
#define HH 100
#define ATT 200
#define DEC_IN 440
#define XCAT 640

// ---------------- scratch (device globals; no allocations allowed) -------------
__device__ float g_emb[S * B * E];
__device__ float g_xw_f[S * B * 4 * HH];
__device__ float g_xw_b[S * B * 4 * HH];
__device__ float g_hs_f[S * B * HH];
__device__ float g_hs_b[S * B * HH];
__device__ float g_cf[B * HH];
__device__ float g_cb[B * HH];
__device__ float g_enc[B * S * H];
__device__ float g_Wcat[4 * H * XCAT];
__device__ float g_WattnT[H * H];
__device__ float g_h[B * H];
__device__ float g_c[B * H];
__device__ float g_Hbuf[T * B * H];
__device__ float g_xcat[B * XCAT];
__device__ float g_z[B * 4 * H];
__device__ float g_gtil[B * H];
__device__ float g_cath[B * 2 * H];

__device__ __forceinline__ float sigf(float x) { return 1.f / (1.f + expf(-x)); }

// ================= fast GEMM: C[M,N] = A[M,K] @ W[N,K]^T (+bias)(+tanh) ========
// Tiles: BM = RPT*16 (RPT=8 -> 128, RPT=4 -> 64), BN=64, BK=16, 256 threads.
// Inner loop uses packed fma.rn.f32x2 (2 MACs/lane/op on sm_103a).
// Requires M % BM == 0. N, K arbitrary (guarded).
template <int RPT>
__global__ void __launch_bounds__(256) k_gemm(
    const float* __restrict__ A, const float* __restrict__ W,
    const float* __restrict__ bias, float* __restrict__ C,
    float* __restrict__ C2, int M, int N, int K, int act)
{
    constexpr int BMv = RPT * 16;
    constexpr int NPF_A = BMv / 64;  // float4 A-loads per thread (2 or 1)
    __shared__ float As[16][BMv];
    __shared__ float Ws[16][64];
    const int bm = blockIdx.y * BMv, bn = blockIdx.x * 64;
    const int tid = threadIdx.x;
    const int ty = tid >> 4, tx = tid & 15;
    const int KT = (K + 15) / 16;

    float4 pfA[NPF_A];
    float4 pfW;

    // ---- prologue load of tile 0 ----
    {
        int kt = 0;
#pragma unroll
        for (int i = 0; i < NPF_A; i++) {
            int f = tid + i * 256;
            int m = f >> 2, kc = f & 3;
            int k = kt * 16 + kc * 4;
            float4 v = make_float4(0.f, 0.f, 0.f, 0.f);
            const float* ap = A + (size_t)(bm + m) * K + k;
            if (k + 3 < K) v = *(const float4*)ap;
            else {
                if (k + 0 < K) v.x = ap[0];
                if (k + 1 < K) v.y = ap[1];
                if (k + 2 < K) v.z = ap[2];
                if (k + 3 < K) v.w = ap[3];
            }
            pfA[i] = v;
        }
        int n = bn + (tid >> 2);
        int k = kt * 16 + (tid & 3) * 4;
        float4 v = make_float4(0.f, 0.f, 0.f, 0.f);
        if (n < N) {
            const float* wp = W + (size_t)n * K + k;
            if (k + 3 < K) v = *(const float4*)wp;
            else {
                if (k + 0 < K) v.x = wp[0];
                if (k + 1 < K) v.y = wp[1];
                if (k + 2 < K) v.z = wp[2];
                if (k + 3 < K) v.w = wp[3];
            }
        }
        pfW = v;
    }

    unsigned long long acc[RPT / 2][4];
#pragma unroll
    for (int p = 0; p < RPT / 2; p++)
#pragma unroll
        for (int j = 0; j < 4; j++) acc[p][j] = 0ull;

    for (int kt = 0; kt < KT; kt++) {
        // store prefetched tile to smem (transposed: As[k][m], Ws[k][n])
#pragma unroll
        for (int i = 0; i < NPF_A; i++) {
            int f = tid + i * 256;
            int m = f >> 2, kc = f & 3;
            As[kc * 4 + 0][m] = pfA[i].x;
            As[kc * 4 + 1][m] = pfA[i].y;
            As[kc * 4 + 2][m] = pfA[i].z;
            As[kc * 4 + 3][m] = pfA[i].w;
        }
        {
            int n = tid >> 2, kc = tid & 3;
            Ws[kc * 4 + 0][n] = pfW.x;
            Ws[kc * 4 + 1][n] = pfW.y;
            Ws[kc * 4 + 2][n] = pfW.z;
            Ws[kc * 4 + 3][n] = pfW.w;
        }
        __syncthreads();

        // prefetch next tile (global loads overlap compute)
        if (kt + 1 < KT) {
            int ktn = kt + 1;
#pragma unroll
            for (int i = 0; i < NPF_A; i++) {
                int f = tid + i * 256;
                int m = f >> 2, kc = f & 3;
                int k = ktn * 16 + kc * 4;
                float4 v = make_float4(0.f, 0.f, 0.f, 0.f);
                const float* ap = A + (size_t)(bm + m) * K + k;
                if (k + 3 < K) v = *(const float4*)ap;
                else {
                    if (k + 0 < K) v.x = ap[0];
                    if (k + 1 < K) v.y = ap[1];
                    if (k + 2 < K) v.z = ap[2];
                    if (k + 3 < K) v.w = ap[3];
                }
                pfA[i] = v;
            }
            int n = bn + (tid >> 2);
            int k = ktn * 16 + (tid & 3) * 4;
            float4 v = make_float4(0.f, 0.f, 0.f, 0.f);
            if (n < N) {
                const float* wp = W + (size_t)n * K + k;
                if (k + 3 < K) v = *(const float4*)wp;
                else {
                    if (k + 0 < K) v.x = wp[0];
                    if (k + 1 < K) v.y = wp[1];
                    if (k + 2 < K) v.z = wp[2];
                    if (k + 3 < K) v.w = wp[3];
                }
            }
            pfW = v;
        }

        // compute 16 kk steps from smem
#pragma unroll
        for (int kk = 0; kk < 16; kk++) {
            unsigned long long a2[RPT / 2];
            const unsigned long long* pa =
                (const unsigned long long*)&As[kk][ty * RPT];
#pragma unroll
            for (int p = 0; p < RPT / 2; p++) a2[p] = pa[p];
            float4 wv = *(const float4*)&Ws[kk][tx * 4];
            unsigned long long w2[4];
            asm("mov.b64 %0, {%1, %2};" : "=l"(w2[0]) : "f"(wv.x), "f"(wv.x));
            asm("mov.b64 %0, {%1, %2};" : "=l"(w2[1]) : "f"(wv.y), "f"(wv.y));
            asm("mov.b64 %0, {%1, %2};" : "=l"(w2[2]) : "f"(wv.z), "f"(wv.z));
            asm("mov.b64 %0, {%1, %2};" : "=l"(w2[3]) : "f"(wv.w), "f"(wv.w));
#pragma unroll
            for (int p = 0; p < RPT / 2; p++)
#pragma unroll
                for (int j = 0; j < 4; j++)
                    asm("fma.rn.f32x2 %0, %1, %2, %0;"
                        : "+l"(acc[p][j]) : "l"(a2[p]), "l"(w2[j]));
        }
        __syncthreads();
    }

    // ---- epilogue ----
    float bv[4];
#pragma unroll
    for (int j = 0; j < 4; j++) {
        int n = bn + tx * 4 + j;
        bv[j] = (bias && n < N) ? bias[n] : 0.f;
    }
#pragma unroll
    for (int p = 0; p < RPT / 2; p++) {
        int m0 = bm + ty * RPT + 2 * p;
#pragma unroll
        for (int j = 0; j < 4; j++) {
            int n = bn + tx * 4 + j;
            if (n >= N) continue;
            float lo, hi;
            asm("mov.b64 {%0, %1}, %2;" : "=f"(lo), "=f"(hi) : "l"(acc[p][j]));
            float v0 = lo + bv[j], v1 = hi + bv[j];
            if (act) { v0 = tanhf(v0); v1 = tanhf(v1); }
            C[(size_t)m0 * N + n] = v0;
            C[(size_t)(m0 + 1) * N + n] = v1;
            if (C2) {
                C2[(size_t)m0 * XCAT + 32 + n] = v0;
                C2[(size_t)(m0 + 1) * XCAT + 32 + n] = v1;
            }
        }
    }
}

// ---------------- embedding ----------------
__global__ void k_embed(const int* __restrict__ sent, const float* __restrict__ src_emb) {
    int i = blockIdx.x * blockDim.x + threadIdx.x;
    if (i < S * B * E) {
        int sb = i >> 6;
        int e = i & 63;
        g_emb[i] = src_emb[(size_t)sent[sb] * E + e];
    }
}

// ---------------- fused bidirectional LSTM encoder (unchanged, works) ----------
#define ENC_BPB 14
#define ENC_SMEM_FLOATS (40000 + ENC_BPB * HH + ENC_BPB * 4 * HH)
__global__ void __launch_bounds__(256) k_encoder(const float* __restrict__ Whh_f,
                                                 const float* __restrict__ Whh_b)
{
    extern __shared__ float sm[];
    float* sW = sm;
    float* sh = sm + 40000;
    float* sz = sm + 40000 + ENC_BPB * HH;

    int dir = blockIdx.x >= 74;
    int lg = dir ? blockIdx.x - 74 : blockIdx.x;
    const float* Whh = dir ? Whh_b : Whh_f;
    const float* xw = dir ? g_xw_b : g_xw_f;
    float* hs = dir ? g_hs_b : g_hs_f;
    float* cg = dir ? g_cb : g_cf;
    int b0 = lg * ENC_BPB;
    int nb = min(ENC_BPB, B - b0);
    int tid = threadIdx.x;

    for (int i = tid; i < 40000; i += 256) sW[i] = Whh[i];
    for (int i = tid; i < ENC_BPB * HH; i += 256) sh[i] = 0.f;
    float creg[6] = {0.f, 0.f, 0.f, 0.f, 0.f, 0.f};
    __syncthreads();

    for (int t = 0; t < S; t++) {
        int tt = dir ? (S - 1 - t) : t;
        if (tid < 200) {
            int jg = tid % 100;
            int bgb = (tid / 100) * 7;
            float acc[4][7];
#pragma unroll
            for (int r = 0; r < 4; r++)
#pragma unroll
                for (int bb = 0; bb < 7; bb++) {
                    int bl = bgb + bb;
                    acc[r][bb] = (bl < nb)
                        ? xw[((size_t)tt * B + (b0 + bl)) * 400 + 4 * jg + r] : 0.f;
                }
            const float4* shv = (const float4*)sh;
            const float4* swv = (const float4*)sW;
            for (int k4 = 0; k4 < 25; k4++) {
                float4 w0 = swv[(4 * jg + 0) * 25 + k4];
                float4 w1 = swv[(4 * jg + 1) * 25 + k4];
                float4 w2 = swv[(4 * jg + 2) * 25 + k4];
                float4 w3 = swv[(4 * jg + 3) * 25 + k4];
#pragma unroll
                for (int bb = 0; bb < 7; bb++) {
                    float4 hv = shv[(bgb + bb) * 25 + k4];
                    acc[0][bb] += w0.x * hv.x + w0.y * hv.y + w0.z * hv.z + w0.w * hv.w;
                    acc[1][bb] += w1.x * hv.x + w1.y * hv.y + w1.z * hv.z + w1.w * hv.w;
                    acc[2][bb] += w2.x * hv.x + w2.y * hv.y + w2.z * hv.z + w2.w * hv.w;
                    acc[3][bb] += w3.x * hv.x + w3.y * hv.y + w3.z * hv.z + w3.w * hv.w;
                }
            }
#pragma unroll
            for (int r = 0; r < 4; r++)
#pragma unroll
                for (int bb = 0; bb < 7; bb++)
                    if (bgb + bb < nb) sz[(bgb + bb) * 400 + 4 * jg + r] = acc[r][bb];
        }
        __syncthreads();
#pragma unroll
        for (int i = 0; i < 6; i++) {
            int pp = tid + i * 256;
            if (pp < nb * HH) {
                int bl = pp / HH, j = pp % HH;
                float zi = sz[bl * 400 + j];
                float zf = sz[bl * 400 + 100 + j];
                float zg = sz[bl * 400 + 200 + j];
                float zo = sz[bl * 400 + 300 + j];
                float cn = sigf(zf) * creg[i] + sigf(zi) * tanhf(zg);
                float hn = sigf(zo) * tanhf(cn);
                creg[i] = cn;
                sh[bl * HH + j] = hn;
                hs[((size_t)tt * B + b0 + bl) * HH + j] = hn;
            }
        }
        __syncthreads();
    }
#pragma unroll
    for (int i = 0; i < 6; i++) {
        int pp = tid + i * 256;
        if (pp < nb * HH) cg[(b0 + pp / HH) * HH + pp % HH] = creg[i];
    }
}

// ---------------- enc concat + transpose to [B, S, 200] ----------------
__global__ void k_concat() {
    int e = blockIdx.x * blockDim.x + threadIdx.x;
    if (e >= B * S * H) return;
    int b = e / (S * H);
    int r = e % (S * H);
    int s = r / H, j = r % H;
    g_enc[e] = (j < HH) ? g_hs_f[((size_t)s * B + b) * HH + j]
                        : g_hs_b[((size_t)s * B + b) * HH + (j - HH)];
}

// ---------------- weight prep ----------------
__global__ void k_prep(const float* __restrict__ Wih_d, const float* __restrict__ Whh_d,
                       const float* __restrict__ W_attn) {
    int i = blockIdx.x * blockDim.x + threadIdx.x;
    if (i < 4 * H * XCAT) {
        int n = i / XCAT, k = i % XCAT;
        g_Wcat[i] = (k < DEC_IN) ? Wih_d[n * DEC_IN + k] : Whh_d[n * H + (k - DEC_IN)];
    } else {
        int i2 = i - 4 * H * XCAT;
        if (i2 < H * H) {
            int k = i2 / H, j = i2 % H;
            g_WattnT[i2] = W_attn[j * H + k];
        }
    }
}

// ---------------- decoder init: h0/c0 + initial xcat (inp=0 | h0) ---------------
__global__ void k_dec_init2() {
    int e = blockIdx.x * blockDim.x + threadIdx.x;
    if (e >= B * XCAT) return;
    int b = e / XCAT, col = e % XCAT;
    if (col < DEC_IN) { g_xcat[e] = 0.f; return; }
    int k = col - DEC_IN;
    int hi = (k >= HH) ? 1 : 0;
    int j = k - hi * HH;
    float hv, cv;
    if (b < 512) {
        int bb = 2 * b + hi;
        hv = g_hs_f[((size_t)(S - 1) * B + bb) * HH + j];
        cv = g_cf[bb * HH + j];
    } else {
        int bb = 2 * (b - 512) + hi;
        hv = g_hs_b[(size_t)bb * HH + j];
        cv = g_cb[bb * HH + j];
    }
    g_h[b * H + k] = hv;
    g_c[b * H + k] = cv;
    g_xcat[e] = hv;
}

// ---------------- fused decoder cell + next-step xcat build ----------------
// Block owns CGB consecutive batch rows entirely (all j), so the parent gather
// for pt==t can be served from this block's smem h.
#define CGB 8
__global__ void __launch_bounds__(256) k_cellx(
    int t, const int* __restrict__ is_prod, const int* __restrict__ prod_ids,
    const int* __restrict__ prim_ids, const int* __restrict__ field_ids,
    const int* __restrict__ parent_t,
    const float* __restrict__ actprod, const float* __restrict__ prim,
    const float* __restrict__ field)
{
    __shared__ float sh[CGB * H];
    int b0 = blockIdx.x * CGB;
    int tid = threadIdx.x;
    for (int e = tid; e < CGB * H; e += 256) {
        int bb = e / H, j = e % H;
        int b = b0 + bb;
        const float* z = g_z + (size_t)b * 4 * H;
        float cn = sigf(z[H + j]) * g_c[b * H + j] + sigf(z[j]) * tanhf(z[2 * H + j]);
        float hn = sigf(z[3 * H + j]) * tanhf(cn);
        g_c[b * H + j] = cn;
        g_h[b * H + j] = hn;
        g_Hbuf[((size_t)t * B + b) * H + j] = hn;
        sh[e] = hn;
    }
    __syncthreads();
    int t1 = t + 1;
    if (t1 >= T) return;
    for (int e = tid; e < CGB * 440; e += 256) {
        int bb = e / 440, cc = e % 440;
        int b = b0 + bb;
        int col;
        float v;
        if (cc < 32) {
            col = cc;
            int idx = t1 * B + b;
            v = (is_prod[idx] == 1) ? actprod[prod_ids[idx] * 32 + cc]
                                    : prim[prim_ids[idx] * 32 + cc];
        } else if (cc < 40) {
            col = 232 + (cc - 32);
            v = field[field_ids[t1 * B + b] * 8 + (cc - 32)];
        } else if (cc < 240) {
            int j = cc - 40;
            col = 240 + j;
            int pt = parent_t[t1 * B + b];
            v = (pt == t) ? sh[bb * H + j] : g_Hbuf[((size_t)pt * B + b) * H + j];
        } else {
            int j = cc - 240;
            col = DEC_IN + j;
            v = sh[bb * H + j];
        }
        g_xcat[(size_t)b * XCAT + col] = v;
    }
}

// ---------------- attention (block per b, SMEM-staged enc) ----------------
#define ATTN_SMEM_FLOATS (S * H + H + S)
__global__ void __launch_bounds__(256) k_attn() {
    extern __shared__ float smem[];
    float* senc = smem;
    float* sg = smem + S * H;
    float* sp = sg + H;
    int b = blockIdx.x, tid = threadIdx.x;

    const float4* src = (const float4*)(g_enc + (size_t)b * S * H);
    float4* dst = (float4*)senc;
    for (int i = tid; i < S * H / 4; i += 256) dst[i] = src[i];
    if (tid < H) sg[tid] = g_gtil[b * H + tid];
    __syncthreads();

    int warp = tid >> 5, lane = tid & 31;
    for (int s = warp; s < S; s += 8) {
        float acc = 0.f;
        for (int k = lane; k < H; k += 32) acc += senc[s * H + k] * sg[k];
#pragma unroll
        for (int o = 16; o; o >>= 1) acc += __shfl_xor_sync(0xffffffffu, acc, o);
        if (lane == 0) sp[s] = acc;
    }
    __syncthreads();
    if (warp == 0) {
        float v0 = sp[lane], v1 = sp[lane + 32], v2 = sp[lane + 64], v3 = sp[lane + 96];
        float m = fmaxf(fmaxf(v0, v1), fmaxf(v2, v3));
#pragma unroll
        for (int o = 16; o; o >>= 1) m = fmaxf(m, __shfl_xor_sync(0xffffffffu, m, o));
        float e0 = expf(v0 - m), e1 = expf(v1 - m), e2 = expf(v2 - m), e3 = expf(v3 - m);
        float ssum = e0 + e1 + e2 + e3;
#pragma unroll
        for (int o = 16; o; o >>= 1) ssum += __shfl_xor_sync(0xffffffffu, ssum, o);
        float inv = 1.f / ssum;
        sp[lane] = e0 * inv; sp[lane + 32] = e1 * inv;
        sp[lane + 64] = e2 * inv; sp[lane + 96] = e3 * inv;
    }
    __syncthreads();
    if (tid < H) {
        float acc = 0.f;
#pragma unroll 8
        for (int s = 0; s < S; s++) acc += sp[s] * senc[s * H + tid];
        g_cath[b * 2 * H + tid] = acc;
        g_cath[b * 2 * H + H + tid] = g_h[b * H + tid];
    }
}

// ---------------- host launch ----------------
extern "C" void kernel_launch(void* const* d_in, const int* in_sizes, int n_in,
                              void* d_out, int out_size) {
    const int* sentences  = (const int*)d_in[0];
    const int* is_prod    = (const int*)d_in[1];
    const int* prod_ids   = (const int*)d_in[2];
    const int* prim_ids   = (const int*)d_in[3];
    const int* field_ids  = (const int*)d_in[4];
    const int* parent_t   = (const int*)d_in[5];
    const float* src_emb  = (const float*)d_in[6];
    const float* actprod_emb = (const float*)d_in[7];
    const float* prim_emb = (const float*)d_in[8];
    const float* field_emb = (const float*)d_in[9];
    const float* Wih_f = (const float*)d_in[10];
    const float* Whh_f = (const float*)d_in[11];
    const float* b_f   = (const float*)d_in[12];
    const float* Wih_b = (const float*)d_in[13];
    const float* Whh_b = (const float*)d_in[14];
    const float* b_b   = (const float*)d_in[15];
    const float* Wih_d = (const float*)d_in[16];
    const float* Whh_d = (const float*)d_in[17];
    const float* b_d   = (const float*)d_in[18];
    const float* W_attn = (const float*)d_in[19];
    const float* W_av   = (const float*)d_in[20];
    float* out = (float*)d_out;

    void *p_emb, *p_xwf, *p_xwb, *p_xcat, *p_Wcat, *p_z, *p_h, *p_WaT, *p_gtil, *p_cath;
    cudaGetSymbolAddress(&p_emb, g_emb);
    cudaGetSymbolAddress(&p_xwf, g_xw_f);
    cudaGetSymbolAddress(&p_xwb, g_xw_b);
    cudaGetSymbolAddress(&p_xcat, g_xcat);
    cudaGetSymbolAddress(&p_Wcat, g_Wcat);
    cudaGetSymbolAddress(&p_z, g_z);
    cudaGetSymbolAddress(&p_h, g_h);
    cudaGetSymbolAddress(&p_WaT, g_WattnT);
    cudaGetSymbolAddress(&p_gtil, g_gtil);
    cudaGetSymbolAddress(&p_cath, g_cath);

    cudaFuncSetAttribute(k_encoder, cudaFuncAttributeMaxDynamicSharedMemorySize,
                         ENC_SMEM_FLOATS * 4);
    cudaFuncSetAttribute(k_attn, cudaFuncAttributeMaxDynamicSharedMemorySize,
                         ATTN_SMEM_FLOATS * 4);

    // 1) embedding
    k_embed<<<(S * B * E + 255) / 256, 256>>>(sentences, src_emb);
    // 2) input projections for both LSTM directions: [131072,64] x [400,64]^T
    {
        dim3 g((400 + 63) / 64, (S * B) / 128);
        k_gemm<8><<<g, 256>>>((const float*)p_emb, Wih_f, b_f, (float*)p_xwf,
                              nullptr, S * B, 400, E, 0);
        k_gemm<8><<<g, 256>>>((const float*)p_emb, Wih_b, b_b, (float*)p_xwb,
                              nullptr, S * B, 400, E, 0);
    }
    // 3) bidirectional encoder
    k_encoder<<<148, 256, ENC_SMEM_FLOATS * 4>>>(Whh_f, Whh_b);
    // 4) enc concat/transpose
    k_concat<<<(B * S * H + 255) / 256, 256>>>();
    // 5) weight prep + decoder init (also builds xcat for t=0)
    k_prep<<<(4 * H * XCAT + H * H + 255) / 256, 256>>>(Wih_d, Whh_d, W_attn);
    k_dec_init2<<<(B * XCAT + 255) / 256, 256>>>();

    dim3 gz((800 + 63) / 64, B / 128);          // 13 x 8
    dim3 gs((200 + 63) / 64, B / 64);           // 4 x 16
    // 6) decoder loop
    for (int t = 0; t < T; t++) {
        // z = xcat @ [Wih_d|Whh_d]^T + b_d
        k_gemm<8><<<gz, 256>>>((const float*)p_xcat, (const float*)p_Wcat, b_d,
                               (float*)p_z, nullptr, B, 4 * H, XCAT, 0);
        // cell + Hbuf + xcat(t+1) except s_att columns
        k_cellx<<<B / CGB, 256>>>(t, is_prod, prod_ids, prim_ids, field_ids,
                                  parent_t, actprod_emb, prim_emb, field_emb);
        // gtil = h @ W_attn  (as A @ WattnT^T)
        k_gemm<4><<<gs, 256>>>((const float*)p_h, (const float*)p_WaT, nullptr,
                               (float*)p_gtil, nullptr, B, H, H, 0);
        // attention -> cath = [ctx, h]
        k_attn<<<B, 256, ATTN_SMEM_FLOATS * 4>>>();
        // s_att = tanh(cath @ W_av^T); dual-store into out[t] and xcat[:,32:232]
        k_gemm<4><<<gs, 256>>>((const float*)p_cath, W_av, nullptr,
                               out + (size_t)t * B * ATT, (float*)p_xcat,
                               B, ATT, 2 * H, 1);
    }
}

// round 4
// speedup vs baseline: 1.4745x; 1.2572x over previous
#include <cuda_runtime.h>
#include <math.h>

#define S 128
#define B 1024
#define T 96
#define E 64
#define H 200
#define HH 100
#define ATT 200
#define DEC_IN 440
#define XCAT 640

// ---------------- scratch (device globals; no allocations allowed) -------------
__device__ float g_emb[S * B * E];
__device__ float g_xw_f[S * B * 4 * HH];
__device__ float g_xw_b[S * B * 4 * HH];
__device__ float g_hs_f[S * B * HH];
__device__ float g_hs_b[S * B * HH];
__device__ float g_cf[B * HH];
__device__ float g_cb[B * HH];
__device__ float g_enc[B * S * H];
__device__ float g_Wcat[4 * H * XCAT];   // gate-interleaved: row r = 4*j+g
__device__ float g_bcat[4 * H];          // interleaved bias
__device__ float g_WattnT[H * H];
__device__ float g_h[B * H];
__device__ float g_c[B * H];
__device__ float g_Hbuf[T * B * H];
__device__ float g_xcat[B * XCAT];
__device__ float g_gtil[B * H];
__device__ float g_cath[B * 2 * H];

__device__ __forceinline__ float sigf(float x) { return 1.f / (1.f + expf(-x)); }

// ================= fast GEMM: C[M,N] = A[M,K] @ W[N,K]^T ========================
// MODE 0: C = A@W^T + bias
// MODE 1: v = tanh(A@W^T); C[m,n] = v; C2[m, 32+n] = v   (dual store)
// MODE 2: gates z = A@W^T + bias (gate-interleaved N); apply LSTM cell in
//         epilogue, write g_h, g_c, g_Hbuf[t]. No C store.
// Tiles: BM = RPT*16, BN=64, BK=16, 256 threads, packed fma.rn.f32x2.
// Requires M % BM == 0. N, K arbitrary (guarded).
template <int RPT, int MODE>
__global__ void __launch_bounds__(256) k_gemm(
    const float* __restrict__ A, const float* __restrict__ W,
    const float* __restrict__ bias, float* __restrict__ C,
    float* __restrict__ C2, int M, int N, int K, int t)
{
    constexpr int BMv = RPT * 16;
    constexpr int NPF_A = BMv / 64;
    __shared__ float As[16][BMv];
    __shared__ float Ws[16][64];
    const int bm = blockIdx.y * BMv, bn = blockIdx.x * 64;
    const int tid = threadIdx.x;
    const int ty = tid >> 4, tx = tid & 15;
    const int KT = (K + 15) / 16;

    float4 pfA[NPF_A];
    float4 pfW;

    // ---- prologue load of tile 0 ----
    {
#pragma unroll
        for (int i = 0; i < NPF_A; i++) {
            int f = tid + i * 256;
            int m = f >> 2, kc = f & 3;
            int k = kc * 4;
            float4 v = make_float4(0.f, 0.f, 0.f, 0.f);
            const float* ap = A + (size_t)(bm + m) * K + k;
            if (k + 3 < K) v = *(const float4*)ap;
            else {
                if (k + 0 < K) v.x = ap[0];
                if (k + 1 < K) v.y = ap[1];
                if (k + 2 < K) v.z = ap[2];
                if (k + 3 < K) v.w = ap[3];
            }
            pfA[i] = v;
        }
        int n = bn + (tid >> 2);
        int k = (tid & 3) * 4;
        float4 v = make_float4(0.f, 0.f, 0.f, 0.f);
        if (n < N) {
            const float* wp = W + (size_t)n * K + k;
            if (k + 3 < K) v = *(const float4*)wp;
            else {
                if (k + 0 < K) v.x = wp[0];
                if (k + 1 < K) v.y = wp[1];
                if (k + 2 < K) v.z = wp[2];
                if (k + 3 < K) v.w = wp[3];
            }
        }
        pfW = v;
    }

    unsigned long long acc[RPT / 2][4];
#pragma unroll
    for (int p = 0; p < RPT / 2; p++)
#pragma unroll
        for (int j = 0; j < 4; j++) acc[p][j] = 0ull;

    for (int kt = 0; kt < KT; kt++) {
#pragma unroll
        for (int i = 0; i < NPF_A; i++) {
            int f = tid + i * 256;
            int m = f >> 2, kc = f & 3;
            As[kc * 4 + 0][m] = pfA[i].x;
            As[kc * 4 + 1][m] = pfA[i].y;
            As[kc * 4 + 2][m] = pfA[i].z;
            As[kc * 4 + 3][m] = pfA[i].w;
        }
        {
            int n = tid >> 2, kc = tid & 3;
            Ws[kc * 4 + 0][n] = pfW.x;
            Ws[kc * 4 + 1][n] = pfW.y;
            Ws[kc * 4 + 2][n] = pfW.z;
            Ws[kc * 4 + 3][n] = pfW.w;
        }
        __syncthreads();

        if (kt + 1 < KT) {
            int ktn = kt + 1;
#pragma unroll
            for (int i = 0; i < NPF_A; i++) {
                int f = tid + i * 256;
                int m = f >> 2, kc = f & 3;
                int k = ktn * 16 + kc * 4;
                float4 v = make_float4(0.f, 0.f, 0.f, 0.f);
                const float* ap = A + (size_t)(bm + m) * K + k;
                if (k + 3 < K) v = *(const float4*)ap;
                else {
                    if (k + 0 < K) v.x = ap[0];
                    if (k + 1 < K) v.y = ap[1];
                    if (k + 2 < K) v.z = ap[2];
                    if (k + 3 < K) v.w = ap[3];
                }
                pfA[i] = v;
            }
            int n = bn + (tid >> 2);
            int k = ktn * 16 + (tid & 3) * 4;
            float4 v = make_float4(0.f, 0.f, 0.f, 0.f);
            if (n < N) {
                const float* wp = W + (size_t)n * K + k;
                if (k + 3 < K) v = *(const float4*)wp;
                else {
                    if (k + 0 < K) v.x = wp[0];
                    if (k + 1 < K) v.y = wp[1];
                    if (k + 2 < K) v.z = wp[2];
                    if (k + 3 < K) v.w = wp[3];
                }
            }
            pfW = v;
        }

#pragma unroll
        for (int kk = 0; kk < 16; kk++) {
            unsigned long long a2[RPT / 2];
            const unsigned long long* pa =
                (const unsigned long long*)&As[kk][ty * RPT];
#pragma unroll
            for (int p = 0; p < RPT / 2; p++) a2[p] = pa[p];
            float4 wv = *(const float4*)&Ws[kk][tx * 4];
            unsigned long long w2[4];
            asm("mov.b64 %0, {%1, %2};" : "=l"(w2[0]) : "f"(wv.x), "f"(wv.x));
            asm("mov.b64 %0, {%1, %2};" : "=l"(w2[1]) : "f"(wv.y), "f"(wv.y));
            asm("mov.b64 %0, {%1, %2};" : "=l"(w2[2]) : "f"(wv.z), "f"(wv.z));
            asm("mov.b64 %0, {%1, %2};" : "=l"(w2[3]) : "f"(wv.w), "f"(wv.w));
#pragma unroll
            for (int p = 0; p < RPT / 2; p++)
#pragma unroll
                for (int j = 0; j < 4; j++)
                    asm("fma.rn.f32x2 %0, %1, %2, %0;"
                        : "+l"(acc[p][j]) : "l"(a2[p]), "l"(w2[j]));
        }
        __syncthreads();
    }

    // ---- epilogue ----
    if (MODE == 2) {
        int n0 = bn + tx * 4;
        if (n0 >= N) return;
        int j = n0 >> 2;   // logical hidden index
        float bz[4];
#pragma unroll
        for (int g = 0; g < 4; g++) bz[g] = bias[n0 + g];
#pragma unroll
        for (int p = 0; p < RPT / 2; p++) {
            int m0 = bm + ty * RPT + 2 * p;
            float zl[4], zh[4];
#pragma unroll
            for (int g = 0; g < 4; g++) {
                float lo, hi;
                asm("mov.b64 {%0, %1}, %2;" : "=f"(lo), "=f"(hi) : "l"(acc[p][g]));
                zl[g] = lo + bz[g];
                zh[g] = hi + bz[g];
            }
#pragma unroll
            for (int r = 0; r < 2; r++) {
                int m = m0 + r;
                float zi = r ? zh[0] : zl[0];
                float zf = r ? zh[1] : zl[1];
                float zg = r ? zh[2] : zl[2];
                float zo = r ? zh[3] : zl[3];
                float c = g_c[m * H + j];
                float cn = sigf(zf) * c + sigf(zi) * tanhf(zg);
                float hn = sigf(zo) * tanhf(cn);
                g_c[m * H + j] = cn;
                g_h[m * H + j] = hn;
                g_Hbuf[((size_t)t * B + m) * H + j] = hn;
            }
        }
        return;
    }

    float bv[4];
#pragma unroll
    for (int j = 0; j < 4; j++) {
        int n = bn + tx * 4 + j;
        bv[j] = (bias && n < N) ? bias[n] : 0.f;
    }
#pragma unroll
    for (int p = 0; p < RPT / 2; p++) {
        int m0 = bm + ty * RPT + 2 * p;
#pragma unroll
        for (int j = 0; j < 4; j++) {
            int n = bn + tx * 4 + j;
            if (n >= N) continue;
            float lo, hi;
            asm("mov.b64 {%0, %1}, %2;" : "=f"(lo), "=f"(hi) : "l"(acc[p][j]));
            float v0 = lo + bv[j], v1 = hi + bv[j];
            if (MODE == 1) { v0 = tanhf(v0); v1 = tanhf(v1); }
            C[(size_t)m0 * N + n] = v0;
            C[(size_t)(m0 + 1) * N + n] = v1;
            if (MODE == 1) {
                C2[(size_t)m0 * XCAT + 32 + n] = v0;
                C2[(size_t)(m0 + 1) * XCAT + 32 + n] = v1;
            }
        }
    }
}

// ---------------- embedding ----------------
__global__ void k_embed(const int* __restrict__ sent, const float* __restrict__ src_emb) {
    int i = blockIdx.x * blockDim.x + threadIdx.x;
    if (i < S * B * E) {
        int sb = i >> 6;
        int e = i & 63;
        g_emb[i] = src_emb[(size_t)sent[sb] * E + e];
    }
}

// ---------------- fused bidirectional LSTM encoder ----------------
#define ENC_BPB 14
#define ENC_SMEM_FLOATS (40000 + ENC_BPB * HH + ENC_BPB * 4 * HH)
__global__ void __launch_bounds__(256) k_encoder(const float* __restrict__ Whh_f,
                                                 const float* __restrict__ Whh_b)
{
    extern __shared__ float sm[];
    float* sW = sm;
    float* sh = sm + 40000;
    float* sz = sm + 40000 + ENC_BPB * HH;

    int dir = blockIdx.x >= 74;
    int lg = dir ? blockIdx.x - 74 : blockIdx.x;
    const float* Whh = dir ? Whh_b : Whh_f;
    const float* xw = dir ? g_xw_b : g_xw_f;
    float* hs = dir ? g_hs_b : g_hs_f;
    float* cg = dir ? g_cb : g_cf;
    int b0 = lg * ENC_BPB;
    int nb = min(ENC_BPB, B - b0);
    int tid = threadIdx.x;

    for (int i = tid; i < 40000; i += 256) sW[i] = Whh[i];
    for (int i = tid; i < ENC_BPB * HH; i += 256) sh[i] = 0.f;
    float creg[6] = {0.f, 0.f, 0.f, 0.f, 0.f, 0.f};
    __syncthreads();

    for (int t = 0; t < S; t++) {
        int tt = dir ? (S - 1 - t) : t;
        if (tid < 200) {
            int jg = tid % 100;
            int bgb = (tid / 100) * 7;
            float acc[4][7];
#pragma unroll
            for (int r = 0; r < 4; r++)
#pragma unroll
                for (int bb = 0; bb < 7; bb++) {
                    int bl = bgb + bb;
                    acc[r][bb] = (bl < nb)
                        ? xw[((size_t)tt * B + (b0 + bl)) * 400 + 4 * jg + r] : 0.f;
                }
            const float4* shv = (const float4*)sh;
            const float4* swv = (const float4*)sW;
            for (int k4 = 0; k4 < 25; k4++) {
                float4 w0 = swv[(4 * jg + 0) * 25 + k4];
                float4 w1 = swv[(4 * jg + 1) * 25 + k4];
                float4 w2 = swv[(4 * jg + 2) * 25 + k4];
                float4 w3 = swv[(4 * jg + 3) * 25 + k4];
#pragma unroll
                for (int bb = 0; bb < 7; bb++) {
                    float4 hv = shv[(bgb + bb) * 25 + k4];
                    acc[0][bb] += w0.x * hv.x + w0.y * hv.y + w0.z * hv.z + w0.w * hv.w;
                    acc[1][bb] += w1.x * hv.x + w1.y * hv.y + w1.z * hv.z + w1.w * hv.w;
                    acc[2][bb] += w2.x * hv.x + w2.y * hv.y + w2.z * hv.z + w2.w * hv.w;
                    acc[3][bb] += w3.x * hv.x + w3.y * hv.y + w3.z * hv.z + w3.w * hv.w;
                }
            }
#pragma unroll
            for (int r = 0; r < 4; r++)
#pragma unroll
                for (int bb = 0; bb < 7; bb++)
                    if (bgb + bb < nb) sz[(bgb + bb) * 400 + 4 * jg + r] = acc[r][bb];
        }
        __syncthreads();
#pragma unroll
        for (int i = 0; i < 6; i++) {
            int pp = tid + i * 256;
            if (pp < nb * HH) {
                int bl = pp / HH, j = pp % HH;
                float zi = sz[bl * 400 + j];
                float zf = sz[bl * 400 + 100 + j];
                float zg = sz[bl * 400 + 200 + j];
                float zo = sz[bl * 400 + 300 + j];
                float cn = sigf(zf) * creg[i] + sigf(zi) * tanhf(zg);
                float hn = sigf(zo) * tanhf(cn);
                creg[i] = cn;
                sh[bl * HH + j] = hn;
                hs[((size_t)tt * B + b0 + bl) * HH + j] = hn;
            }
        }
        __syncthreads();
    }
#pragma unroll
    for (int i = 0; i < 6; i++) {
        int pp = tid + i * 256;
        if (pp < nb * HH) cg[(b0 + pp / HH) * HH + pp % HH] = creg[i];
    }
}

// ---------------- enc concat + transpose to [B, S, 200] ----------------
__global__ void k_concat() {
    int e = blockIdx.x * blockDim.x + threadIdx.x;
    if (e >= B * S * H) return;
    int b = e / (S * H);
    int r = e % (S * H);
    int s = r / H, j = r % H;
    g_enc[e] = (j < HH) ? g_hs_f[((size_t)s * B + b) * HH + j]
                        : g_hs_b[((size_t)s * B + b) * HH + (j - HH)];
}

// ---------------- weight prep: gate-interleaved Wcat/bcat + WattnT --------------
__global__ void k_prep(const float* __restrict__ Wih_d, const float* __restrict__ Whh_d,
                       const float* __restrict__ b_d, const float* __restrict__ W_attn) {
    int i = blockIdx.x * blockDim.x + threadIdx.x;
    if (i < 4 * H * XCAT) {
        int r = i / XCAT, k = i % XCAT;
        int src = (r & 3) * H + (r >> 2);   // gate-major original row
        g_Wcat[i] = (k < DEC_IN) ? Wih_d[src * DEC_IN + k]
                                 : Whh_d[src * H + (k - DEC_IN)];
    } else {
        int i2 = i - 4 * H * XCAT;
        if (i2 < H * H) {
            int k = i2 / H, j = i2 % H;
            g_WattnT[i2] = W_attn[j * H + k];
        } else {
            int r = i2 - H * H;
            if (r < 4 * H) g_bcat[r] = b_d[(r & 3) * H + (r >> 2)];
        }
    }
}

// ---------------- decoder init: h0/c0 + initial xcat (inp=0 | h0) ---------------
__global__ void k_dec_init2() {
    int e = blockIdx.x * blockDim.x + threadIdx.x;
    if (e >= B * XCAT) return;
    int b = e / XCAT, col = e % XCAT;
    if (col < DEC_IN) { g_xcat[e] = 0.f; return; }
    int k = col - DEC_IN;
    int hi = (k >= HH) ? 1 : 0;
    int j = k - hi * HH;
    float hv, cv;
    if (b < 512) {
        int bb = 2 * b + hi;
        hv = g_hs_f[((size_t)(S - 1) * B + bb) * HH + j];
        cv = g_cf[bb * HH + j];
    } else {
        int bb = 2 * (b - 512) + hi;
        hv = g_hs_b[(size_t)bb * HH + j];
        cv = g_cb[bb * HH + j];
    }
    g_h[b * H + k] = hv;
    g_c[b * H + k] = cv;
    g_xcat[e] = hv;
}

// ---------------- attention: online softmax, single pass over enc --------------
// One block per batch row b, 8 warps x 16 enc rows each. Also fuses the
// next-step xcat gather build (all cols except s_att[32:232], done by out-GEMM).
__global__ void __launch_bounds__(256) k_attn2(
    int t, const int* __restrict__ is_prod, const int* __restrict__ prod_ids,
    const int* __restrict__ prim_ids, const int* __restrict__ field_ids,
    const int* __restrict__ parent_t,
    const float* __restrict__ actprod, const float* __restrict__ prim,
    const float* __restrict__ field)
{
    __shared__ float sg[H];
    __shared__ float wm[8], ws[8];
    __shared__ float wctx[8][H];
    int b = blockIdx.x, tid = threadIdx.x;
    int warp = tid >> 5, lane = tid & 31;

    if (tid < H) sg[tid] = g_gtil[b * H + tid];
    __syncthreads();

    float sgr[7];
#pragma unroll
    for (int i = 0; i < 7; i++) {
        int k = lane + 32 * i;
        sgr[i] = (k < H) ? sg[k] : 0.f;
    }

    float m = -1e30f, zsum = 0.f;
    float ctx[7] = {0.f, 0.f, 0.f, 0.f, 0.f, 0.f, 0.f};
    const float* eb = g_enc + (size_t)b * S * H;
#pragma unroll 2
    for (int si = 0; si < 16; si++) {
        int s = warp * 16 + si;
        const float* er = eb + s * H;
        float v[7];
#pragma unroll
        for (int i = 0; i < 7; i++) {
            int k = lane + 32 * i;
            v[i] = (k < H) ? er[k] : 0.f;
        }
        float sc = 0.f;
#pragma unroll
        for (int i = 0; i < 7; i++) sc += v[i] * sgr[i];
#pragma unroll
        for (int o = 16; o; o >>= 1) sc += __shfl_xor_sync(0xffffffffu, sc, o);
        float mn = fmaxf(m, sc);
        float corr = expf(m - mn);
        float e = expf(sc - mn);
        zsum = zsum * corr + e;
#pragma unroll
        for (int i = 0; i < 7; i++) ctx[i] = ctx[i] * corr + e * v[i];
        m = mn;
    }
    if (lane == 0) { wm[warp] = m; ws[warp] = zsum; }
#pragma unroll
    for (int i = 0; i < 7; i++) {
        int k = lane + 32 * i;
        if (k < H) wctx[warp][k] = ctx[i];
    }
    __syncthreads();

    // combine 8 warps
    float M = wm[0];
#pragma unroll
    for (int w = 1; w < 8; w++) M = fmaxf(M, wm[w]);
    float Z = 0.f;
#pragma unroll
    for (int w = 0; w < 8; w++) Z = fmaf(ws[w], expf(wm[w] - M), Z);
    float invZ = 1.f / Z;
    if (tid < H) {
        float cx = 0.f;
#pragma unroll
        for (int w = 0; w < 8; w++) cx = fmaf(wctx[w][tid], expf(wm[w] - M), cx);
        cx *= invZ;
        g_cath[b * 2 * H + tid] = cx;
        g_cath[b * 2 * H + H + tid] = g_h[b * H + tid];
    }

    // build xcat(t+1) except cols [32,232) (s_att, written by out-GEMM)
    int t1 = t + 1;
    if (t1 >= T) return;
    for (int cc = tid; cc < 440; cc += 256) {
        int col;
        float v;
        if (cc < 32) {
            col = cc;
            int idx = t1 * B + b;
            v = (is_prod[idx] == 1) ? actprod[prod_ids[idx] * 32 + cc]
                                    : prim[prim_ids[idx] * 32 + cc];
        } else if (cc < 40) {
            col = 232 + (cc - 32);
            v = field[field_ids[t1 * B + b] * 8 + (cc - 32)];
        } else if (cc < 240) {
            int j = cc - 40;
            col = 240 + j;
            int pt = parent_t[t1 * B + b];
            v = g_Hbuf[((size_t)pt * B + b) * H + j];
        } else {
            int j = cc - 240;
            col = DEC_IN + j;
            v = g_h[b * H + j];
        }
        g_xcat[(size_t)b * XCAT + col] = v;
    }
}

// ---------------- host launch ----------------
extern "C" void kernel_launch(void* const* d_in, const int* in_sizes, int n_in,
                              void* d_out, int out_size) {
    const int* sentences  = (const int*)d_in[0];
    const int* is_prod    = (const int*)d_in[1];
    const int* prod_ids   = (const int*)d_in[2];
    const int* prim_ids   = (const int*)d_in[3];
    const int* field_ids  = (const int*)d_in[4];
    const int* parent_t   = (const int*)d_in[5];
    const float* src_emb  = (const float*)d_in[6];
    const float* actprod_emb = (const float*)d_in[7];
    const float* prim_emb = (const float*)d_in[8];
    const float* field_emb = (const float*)d_in[9];
    const float* Wih_f = (const float*)d_in[10];
    const float* Whh_f = (const float*)d_in[11];
    const float* b_f   = (const float*)d_in[12];
    const float* Wih_b = (const float*)d_in[13];
    const float* Whh_b = (const float*)d_in[14];
    const float* b_b   = (const float*)d_in[15];
    const float* Wih_d = (const float*)d_in[16];
    const float* Whh_d = (const float*)d_in[17];
    const float* b_d   = (const float*)d_in[18];
    const float* W_attn = (const float*)d_in[19];
    const float* W_av   = (const float*)d_in[20];
    float* out = (float*)d_out;

    void *p_emb, *p_xwf, *p_xwb, *p_xcat, *p_Wcat, *p_bcat, *p_h, *p_WaT, *p_gtil, *p_cath;
    cudaGetSymbolAddress(&p_emb, g_emb);
    cudaGetSymbolAddress(&p_xwf, g_xw_f);
    cudaGetSymbolAddress(&p_xwb, g_xw_b);
    cudaGetSymbolAddress(&p_xcat, g_xcat);
    cudaGetSymbolAddress(&p_Wcat, g_Wcat);
    cudaGetSymbolAddress(&p_bcat, g_bcat);
    cudaGetSymbolAddress(&p_h, g_h);
    cudaGetSymbolAddress(&p_WaT, g_WattnT);
    cudaGetSymbolAddress(&p_gtil, g_gtil);
    cudaGetSymbolAddress(&p_cath, g_cath);

    cudaFuncSetAttribute(k_encoder, cudaFuncAttributeMaxDynamicSharedMemorySize,
                         ENC_SMEM_FLOATS * 4);

    // 1) embedding
    k_embed<<<(S * B * E + 255) / 256, 256>>>(sentences, src_emb);
    // 2) input projections for both LSTM directions
    {
        dim3 g((400 + 63) / 64, (S * B) / 128);
        k_gemm<8, 0><<<g, 256>>>((const float*)p_emb, Wih_f, b_f, (float*)p_xwf,
                                 nullptr, S * B, 400, E, 0);
        k_gemm<8, 0><<<g, 256>>>((const float*)p_emb, Wih_b, b_b, (float*)p_xwb,
                                 nullptr, S * B, 400, E, 0);
    }
    // 3) bidirectional encoder
    k_encoder<<<148, 256, ENC_SMEM_FLOATS * 4>>>(Whh_f, Whh_b);
    // 4) enc concat/transpose
    k_concat<<<(B * S * H + 255) / 256, 256>>>();
    // 5) weight prep + decoder init (also builds xcat for t=0)
    k_prep<<<(4 * H * XCAT + H * H + 4 * H + 255) / 256, 256>>>(Wih_d, Whh_d, b_d, W_attn);
    k_dec_init2<<<(B * XCAT + 255) / 256, 256>>>();

    dim3 gz((800 + 63) / 64, B / 64);   // 13 x 16, BM=64
    dim3 gs((200 + 63) / 64, B / 64);   // 4 x 16
    // 6) decoder loop: 4 kernels per step
    for (int t = 0; t < T; t++) {
        // z = xcat @ Wcat^T + bcat (gate-interleaved), fused LSTM cell ->
        // writes g_h, g_c, g_Hbuf[t]; z never hits memory.
        k_gemm<4, 2><<<gz, 256>>>((const float*)p_xcat, (const float*)p_Wcat,
                                  (const float*)p_bcat, nullptr, nullptr,
                                  B, 4 * H, XCAT, t);
        // gtil = h @ WattnT^T
        k_gemm<4, 0><<<gs, 256>>>((const float*)p_h, (const float*)p_WaT, nullptr,
                                  (float*)p_gtil, nullptr, B, H, H, 0);
        // attention (online softmax, single pass) + cath + xcat(t+1) gathers
        k_attn2<<<B, 256>>>(t, is_prod, prod_ids, prim_ids, field_ids,
                            parent_t, actprod_emb, prim_emb, field_emb);
        // s_att = tanh(cath @ W_av^T); dual store: out[t] and xcat[:,32:232]
        k_gemm<4, 1><<<gs, 256>>>((const float*)p_cath, W_av, nullptr,
                                  out + (size_t)t * B * ATT, (float*)p_xcat,
                                  B, ATT, 2 * H, 0);
    }
}